// round 5
// baseline (speedup 1.0000x reference)
#include <cuda_runtime.h>
#include <math.h>

// ---------------------------------------------------------------------------
// NormDist-IBP AlexNet:
//   5x Lp(p=8) distance convs with interval bounds (c, l, u), relu fused,
//   2x maxpool 3x3/s2, 3x interval-bound linear, final negate/swap.
// Layout everywhere: [B, C, H, W] row-major, fp32.
// ---------------------------------------------------------------------------

#define MAXBUF 345600  // 16*96*15*15 (largest intermediate)

__device__ float g_ac[MAXBUF], g_al[MAXBUF], g_ah[MAXBUF];
__device__ float g_bc[MAXBUF], g_bl[MAXBUF], g_bh[MAXBUF];
__device__ float g_w1t[96 * 147];
__device__ float g_w2t[256 * 2400];
__device__ float g_w3t[384 * 2304];
__device__ float g_w4t[384 * 3456];
__device__ float g_w5t[256 * 3456];

// [O, F] -> [F, O] (coalesced weight reads in the conv inner loop), with
// optional pre-scale folded in.
__global__ void transpose_scale_kernel(const float* __restrict__ w,
                                       float* __restrict__ wt,
                                       int O, int F, float sc) {
    int i = blockIdx.x * blockDim.x + threadIdx.x;
    if (i < O * F) {
        int o = i / F;
        int f = i - o * F;
        wt[f * O + o] = w[i] * sc;
    }
}

// NormDist conv + fused relu.
// Block: one (batch, output pixel). Thread: one output channel.
// Patches (c, l, h) staged in smem in F-tiles; weights streamed from L2,
// coalesced via the [F, O] transpose.
template <int B_, int C, int H, int W, int K, int S, int PAD, int O, int Ho, int Wo>
__global__ void __launch_bounds__(O) ndconv_kernel(
    const float* __restrict__ ic, const float* __restrict__ il,
    const float* __restrict__ ih, const float* __restrict__ wt,
    float* __restrict__ ocp, float* __restrict__ olp, float* __restrict__ ohp,
    float SC, float INV_SC) {
    constexpr int F = C * K * K;
    constexpr int FT = (F < 1152) ? F : 1152;
    __shared__ float spc[FT], spl[FT], sph[FT];

    const int pix = blockIdx.x;
    const int b = blockIdx.y;
    const int ho = pix / Wo, wo = pix - ho * Wo;
    const int o = threadIdx.x;

    float ac = 0.f, al = 0.f, ah = 0.f;

    for (int fbase = 0; fbase < F; fbase += FT) {
        const int cnt = (F - fbase < FT) ? (F - fbase) : FT;
        __syncthreads();
        for (int t = threadIdx.x; t < cnt; t += O) {
            int f = fbase + t;
            int cch = f / (K * K);
            int r = f - cch * (K * K);
            int ky = r / K;
            int kx = r - ky * K;
            int y = ho * S - PAD + ky;
            int x = wo * S - PAD + kx;
            float vc = 0.f, vl = 0.f, vh = 0.f;
            if (y >= 0 && y < H && x >= 0 && x < W) {
                int idx = ((b * C + cch) * H + y) * W + x;
                vc = ic[idx] * SC;
                vl = il[idx] * SC;
                vh = ih[idx] * SC;
            }
            spc[t] = vc;
            spl[t] = vl;
            sph[t] = vh;
        }
        __syncthreads();

        const float* wp = wt + (size_t)fbase * O + o;
        if (cnt == FT) {
#pragma unroll 8
            for (int t = 0; t < FT; t++) {
                float w = wp[t * O];
                float pc = spc[t], pl = spl[t], ph = sph[t];
                float s1 = pc - w;
                float s2 = pl - w;
                float s3 = ph - w;
                // center: |pc-w|^8 == (pc-w)^8
                float c2 = s1 * s1, c4 = c2 * c2;
                ac = fmaf(c4, c4, ac);
                // lower: max(pl-w, w-ph, 0)^8
                float dl = fmaxf(fmaxf(s2, -s3), 0.0f);
                float l2 = dl * dl, l4 = l2 * l2;
                al = fmaf(l4, l4, al);
                // upper: max(|pl-w|, |ph-w|)^8 via max of squares
                float h2 = fmaxf(s2 * s2, s3 * s3);
                float h4 = h2 * h2;
                ah = fmaf(h4, h4, ah);
            }
        } else {
#pragma unroll 4
            for (int t = 0; t < cnt; t++) {
                float w = wp[t * O];
                float pc = spc[t], pl = spl[t], ph = sph[t];
                float s1 = pc - w;
                float s2 = pl - w;
                float s3 = ph - w;
                float c2 = s1 * s1, c4 = c2 * c2;
                ac = fmaf(c4, c4, ac);
                float dl = fmaxf(fmaxf(s2, -s3), 0.0f);
                float l2 = dl * dl, l4 = l2 * l2;
                al = fmaf(l4, l4, al);
                float h2 = fmaxf(s2 * s2, s3 * s3);
                float h4 = h2 * h2;
                ah = fmaf(h4, h4, ah);
            }
        }
    }

    // s^(1/8) = sqrt(sqrt(sqrt(s))); relu fused (values already >= 0).
    int oidx = ((b * O + o) * Ho + ho) * Wo + wo;
    ocp[oidx] = fmaxf(sqrtf(sqrtf(sqrtf(ac))) * INV_SC, 0.f);
    olp[oidx] = fmaxf(sqrtf(sqrtf(sqrtf(al))) * INV_SC, 0.f);
    ohp[oidx] = fmaxf(sqrtf(sqrtf(sqrtf(ah))) * INV_SC, 0.f);
}

// 3x3 stride-2 VALID maxpool over all three bound tensors.
__global__ void maxpool_kernel(const float* __restrict__ ic,
                               const float* __restrict__ il,
                               const float* __restrict__ ih,
                               float* __restrict__ oc, float* __restrict__ ol,
                               float* __restrict__ oh, int BC, int H, int W,
                               int Ho, int Wo) {
    int i = blockIdx.x * blockDim.x + threadIdx.x;
    if (i >= BC * Ho * Wo) return;
    int wo = i % Wo;
    int t = i / Wo;
    int ho = t % Ho;
    int bc = t / Ho;
    int base = bc * H * W;
    float mc = -INFINITY, ml = -INFINITY, mh = -INFINITY;
#pragma unroll
    for (int ky = 0; ky < 3; ky++) {
#pragma unroll
        for (int kx = 0; kx < 3; kx++) {
            int idx = base + (2 * ho + ky) * W + (2 * wo + kx);
            mc = fmaxf(mc, ic[idx]);
            ml = fmaxf(ml, il[idx]);
            mh = fmaxf(mh, ih[idx]);
        }
    }
    oc[i] = mc;
    ol[i] = ml;
    oh[i] = mh;
}

// Interval-bound linear. Warp per (b, out_feature): coalesced row reads of W.
// mode 0: relu, write to oc/ol/oh. mode 1: +bias, negate/swap into fout.
__global__ void linear_bound_kernel(
    const float* __restrict__ ic, const float* __restrict__ il,
    const float* __restrict__ ih, const float* __restrict__ Wm,
    const float* __restrict__ bias, float* __restrict__ oc,
    float* __restrict__ ol, float* __restrict__ oh, float* __restrict__ fout,
    int IN, int OUT, int B, int mode) {
    int gw = (blockIdx.x * blockDim.x + threadIdx.x) >> 5;
    int lane = threadIdx.x & 31;
    if (gw >= B * OUT) return;
    int b = gw / OUT;
    int j = gw - b * OUT;
    const float* wr = Wm + (size_t)j * IN;
    const float* pc = ic + (size_t)b * IN;
    const float* pl = il + (size_t)b * IN;
    const float* ph = ih + (size_t)b * IN;
    float sc = 0.f, sm = 0.f, sr = 0.f;
    for (int i = lane; i < IN; i += 32) {
        float w = wr[i];
        float cv = pc[i], lv = pl[i], hv = ph[i];
        sc = fmaf(cv, w, sc);
        sm = fmaf((lv + hv) * 0.5f, w, sm);
        sr = fmaf((hv - lv) * 0.5f, fabsf(w), sr);
    }
#pragma unroll
    for (int off = 16; off; off >>= 1) {
        sc += __shfl_xor_sync(0xffffffffu, sc, off);
        sm += __shfl_xor_sync(0xffffffffu, sm, off);
        sr += __shfl_xor_sync(0xffffffffu, sr, off);
    }
    if (lane == 0) {
        if (mode == 0) {
            oc[gw] = fmaxf(sc, 0.f);
            ol[gw] = fmaxf(sm - sr, 0.f);
            oh[gw] = fmaxf(sm + sr, 0.f);
        } else {
            float bj = bias[j];
            float c = sc + bj;
            float m = sm + bj;
            fout[gw] = -c;                       // -center
            fout[B * OUT + gw] = -(m + sr);      // -upper
            fout[2 * B * OUT + gw] = -(m - sr);  // -lower
        }
    }
}

static inline int cdiv(int a, int b) { return (a + b - 1) / b; }

extern "C" void kernel_launch(void* const* d_in, const int* in_sizes, int n_in,
                              void* d_out, int out_size) {
    const float* x = (const float*)d_in[0];
    const float* lo = (const float*)d_in[1];
    const float* hi = (const float*)d_in[2];
    const float* w1 = (const float*)d_in[3];
    const float* w2 = (const float*)d_in[4];
    const float* w3 = (const float*)d_in[5];
    const float* w4 = (const float*)d_in[6];
    const float* w5 = (const float*)d_in[7];
    const float* fw1 = (const float*)d_in[8];
    const float* fw2 = (const float*)d_in[9];
    const float* fw3 = (const float*)d_in[10];
    const float* fb3 = (const float*)d_in[11];
    float* out = (float*)d_out;

    float *ac, *al, *ah, *bc, *bl, *bh;
    float *w1t, *w2t, *w3t, *w4t, *w5t;
    cudaGetSymbolAddress((void**)&ac, g_ac);
    cudaGetSymbolAddress((void**)&al, g_al);
    cudaGetSymbolAddress((void**)&ah, g_ah);
    cudaGetSymbolAddress((void**)&bc, g_bc);
    cudaGetSymbolAddress((void**)&bl, g_bl);
    cudaGetSymbolAddress((void**)&bh, g_bh);
    cudaGetSymbolAddress((void**)&w1t, g_w1t);
    cudaGetSymbolAddress((void**)&w2t, g_w2t);
    cudaGetSymbolAddress((void**)&w3t, g_w3t);
    cudaGetSymbolAddress((void**)&w4t, g_w4t);
    cudaGetSymbolAddress((void**)&w5t, g_w5t);

    const float SC = 1.0f, ISC = 1.0f;  // range analysis: d^8 fits fp32 directly

    // Weight transposes [O,F] -> [F,O]
    transpose_scale_kernel<<<cdiv(96 * 147, 256), 256>>>(w1, w1t, 96, 147, SC);
    transpose_scale_kernel<<<cdiv(256 * 2400, 256), 256>>>(w2, w2t, 256, 2400, SC);
    transpose_scale_kernel<<<cdiv(384 * 2304, 256), 256>>>(w3, w3t, 384, 2304, SC);
    transpose_scale_kernel<<<cdiv(384 * 3456, 256), 256>>>(w4, w4t, 384, 3456, SC);
    transpose_scale_kernel<<<cdiv(256 * 3456, 256), 256>>>(w5, w5t, 256, 3456, SC);

    // conv1: [16,3,32,32] k7 s2 p2 -> [16,96,15,15], relu fused
    ndconv_kernel<16, 3, 32, 32, 7, 2, 2, 96, 15, 15>
        <<<dim3(225, 16), 96>>>(x, lo, hi, w1t, ac, al, ah, SC, ISC);
    // pool1: 15 -> 7
    maxpool_kernel<<<cdiv(16 * 96 * 49, 256), 256>>>(ac, al, ah, bc, bl, bh,
                                                     16 * 96, 15, 15, 7, 7);
    // conv2: k5 s1 p2 -> [16,256,7,7]
    ndconv_kernel<16, 96, 7, 7, 5, 1, 2, 256, 7, 7>
        <<<dim3(49, 16), 256>>>(bc, bl, bh, w2t, ac, al, ah, SC, ISC);
    // pool2: 7 -> 3
    maxpool_kernel<<<cdiv(16 * 256 * 9, 256), 256>>>(ac, al, ah, bc, bl, bh,
                                                     16 * 256, 7, 7, 3, 3);
    // conv3: k3 s1 p1 -> [16,384,3,3]
    ndconv_kernel<16, 256, 3, 3, 3, 1, 1, 384, 3, 3>
        <<<dim3(9, 16), 384>>>(bc, bl, bh, w3t, ac, al, ah, SC, ISC);
    // conv4
    ndconv_kernel<16, 384, 3, 3, 3, 1, 1, 384, 3, 3>
        <<<dim3(9, 16), 384>>>(ac, al, ah, w4t, bc, bl, bh, SC, ISC);
    // conv5 -> [16,256,3,3] == [16,2304] flattened
    ndconv_kernel<16, 384, 3, 3, 3, 1, 1, 256, 3, 3>
        <<<dim3(9, 16), 256>>>(bc, bl, bh, w5t, ac, al, ah, SC, ISC);

    // fc1: 2304 -> 1024 (+relu). 16*1024 warps, 8 warps/block.
    linear_bound_kernel<<<cdiv(16 * 1024, 8), 256>>>(
        ac, al, ah, fw1, nullptr, bc, bl, bh, nullptr, 2304, 1024, 16, 0);
    // fc2: 1024 -> 512 (+relu)
    linear_bound_kernel<<<cdiv(16 * 512, 8), 256>>>(
        bc, bl, bh, fw2, nullptr, ac, al, ah, nullptr, 1024, 512, 16, 0);
    // fc3: 512 -> 10 (+bias), final negate/swap into d_out [(-c, -u, -l)]
    linear_bound_kernel<<<cdiv(16 * 10, 8), 256>>>(
        ac, al, ah, fw3, fb3, nullptr, nullptr, nullptr, out, 512, 10, 16, 1);
}

// round 6
// speedup vs baseline: 1.2450x; 1.2450x over previous
#include <cuda_runtime.h>
#include <math.h>

// ---------------------------------------------------------------------------
// NormDist-IBP AlexNet, f32x2-packed edition.
//   5x Lp(p=8) distance convs with interval bounds (c,l,u), relu fused,
//   2x maxpool 3x3/s2, 3x interval-bound linear, final negate/swap.
// Weights pre-packed as negated interleaved pairs: [(FP/2), O, 2] so the
// inner loop is LDG.64 + 3x LDS.64 + 13 packed f32x2 ops + 6 scalar FMNMX
// per TWO taps.
// ---------------------------------------------------------------------------

using u64 = unsigned long long;

__device__ __forceinline__ u64 add2(u64 a, u64 b) {
    u64 d; asm("add.rn.f32x2 %0,%1,%2;" : "=l"(d) : "l"(a), "l"(b)); return d;
}
__device__ __forceinline__ u64 mul2(u64 a, u64 b) {
    u64 d; asm("mul.rn.f32x2 %0,%1,%2;" : "=l"(d) : "l"(a), "l"(b)); return d;
}
__device__ __forceinline__ u64 fma2(u64 a, u64 b, u64 c) {
    u64 d; asm("fma.rn.f32x2 %0,%1,%2,%3;" : "=l"(d) : "l"(a), "l"(b), "l"(c)); return d;
}
__device__ __forceinline__ void unpk(u64 v, float& lo, float& hi) {
    asm("mov.b64 {%0,%1},%2;" : "=f"(lo), "=f"(hi) : "l"(v));
}
__device__ __forceinline__ u64 pk2(float lo, float hi) {
    u64 d; asm("mov.b64 %0,{%1,%2};" : "=l"(d) : "f"(lo), "f"(hi)); return d;
}

#define MAXBUF 345600  // 16*96*15*15 (largest intermediate)

__device__ float g_ac[MAXBUF], g_al[MAXBUF], g_ah[MAXBUF];
__device__ float g_bc[MAXBUF], g_bl[MAXBUF], g_bh[MAXBUF];
__device__ float g_w1t[96 * 148];
__device__ float g_w2t[256 * 2400];
__device__ float g_w3t[384 * 2304];
__device__ float g_w4t[384 * 3456];
__device__ float g_w5t[256 * 3456];

// [O, F] -> negated pair-interleaved [(FP/2), O, 2], tiled transpose through
// smem so both the read and the write are coalesced. Pads f in [F, FP) with 0.
__global__ void pack_weights(const float* __restrict__ w, float2* __restrict__ dst,
                             int O, int F, int J /* = FP/2 */) {
    __shared__ float tile[32][33];
    int fb = blockIdx.x * 32, ob = blockIdx.y * 32;
    int tx = threadIdx.x, ty = threadIdx.y;  // 32 x 8
#pragma unroll
    for (int r = 0; r < 32; r += 8) {
        int o = ob + ty + r, f = fb + tx;
        tile[ty + r][tx] = (o < O && f < F) ? w[(size_t)o * F + f] : 0.f;
    }
    __syncthreads();
#pragma unroll
    for (int r = 0; r < 16; r += 8) {
        int k = ty + r;          // pair index within tile
        int j = (fb >> 1) + k;   // global pair index
        int o = ob + tx;
        if (o < O && j < J)
            dst[(size_t)j * O + o] =
                make_float2(-tile[tx][2 * k], -tile[tx][2 * k + 1]);
    }
}

// NormDist conv + fused relu, f32x2 packed over adjacent F-taps.
// Block: (batch, PIX output pixels). Thread: one output channel.
template <int PIX, int C, int H, int W, int K, int S, int PAD, int O, int Ho,
          int Wo, int FP, int FT>
__global__ void __launch_bounds__(O) ndconv_kernel(
    const float* __restrict__ ic, const float* __restrict__ il,
    const float* __restrict__ ih, const float* __restrict__ wt,
    float* __restrict__ ocp, float* __restrict__ olp, float* __restrict__ ohp) {
    static_assert(FP % FT == 0 && FT % 2 == 0, "tile must divide padded F");
    constexpr int F = C * K * K;
    constexpr int L = Ho * Wo;
    __shared__ alignas(16) float spc[PIX][FT], spl[PIX][FT], sph[PIX][FT];

    const int b = blockIdx.y;
    const int o = threadIdx.x;
    int pix[PIX];
    pix[0] = blockIdx.x * PIX;
#pragma unroll
    for (int p = 1; p < PIX; p++) pix[p] = min(pix[0] + p, L - 1);

    u64 accc[PIX], accl[PIX], acch[PIX];
#pragma unroll
    for (int p = 0; p < PIX; p++) accc[p] = accl[p] = acch[p] = 0ull;

    for (int fbase = 0; fbase < FP; fbase += FT) {
        __syncthreads();
#pragma unroll
        for (int p = 0; p < PIX; p++) {
            int ho = pix[p] / Wo, wo = pix[p] - ho * Wo;
            for (int t = threadIdx.x; t < FT; t += O) {
                int f = fbase + t;
                float vc = 0.f, vl = 0.f, vh = 0.f;
                if (f < F) {
                    int cch = f / (K * K);
                    int r = f - cch * (K * K);
                    int ky = r / K, kx = r - ky * K;
                    int y = ho * S - PAD + ky;
                    int x = wo * S - PAD + kx;
                    if ((unsigned)y < (unsigned)H && (unsigned)x < (unsigned)W) {
                        int idx = ((b * C + cch) * H + y) * W + x;
                        vc = ic[idx]; vl = il[idx]; vh = ih[idx];
                    }
                }
                spc[p][t] = vc; spl[p][t] = vl; sph[p][t] = vh;
            }
        }
        __syncthreads();

        const u64* wq = reinterpret_cast<const u64*>(wt) +
                        (size_t)(fbase >> 1) * O + o;
#pragma unroll 4
        for (int tj = 0; tj < FT / 2; tj++) {
            u64 w = __ldg(wq + (size_t)tj * O);  // { -w[2f], -w[2f+1] }
#pragma unroll
            for (int p = 0; p < PIX; p++) {
                u64 pc = reinterpret_cast<const u64*>(spc[p])[tj];
                u64 pl = reinterpret_cast<const u64*>(spl[p])[tj];
                u64 ph = reinterpret_cast<const u64*>(sph[p])[tj];
                u64 s1 = add2(pc, w);  // pc - w
                u64 s2 = add2(pl, w);  // pl - w
                u64 s3 = add2(ph, w);  // ph - w
                // center: (pc-w)^8
                u64 c2 = mul2(s1, s1);
                u64 c4 = mul2(c2, c2);
                accc[p] = fma2(c4, c4, accc[p]);
                // squares for the bound paths
                u64 a = mul2(s2, s2);
                u64 bb = mul2(s3, s3);
                float a0, a1, b0, b1, s20, s21, s30, s31;
                unpk(a, a0, a1); unpk(bb, b0, b1);
                unpk(s2, s20, s21); unpk(s3, s30, s31);
                // upper: max(|s2|,|s3|)^8 via max of squares
                u64 h2 = pk2(fmaxf(a0, b0), fmaxf(a1, b1));
                u64 h4 = mul2(h2, h2);
                acch[p] = fma2(h4, h4, acch[p]);
                // lower: max(s2, -s3, 0)^8
                float dl0 = fmaxf(fmaxf(s20, -s30), 0.f);
                float dl1 = fmaxf(fmaxf(s21, -s31), 0.f);
                u64 dl = pk2(dl0, dl1);
                u64 l2 = mul2(dl, dl);
                u64 l4 = mul2(l2, l2);
                accl[p] = fma2(l4, l4, accl[p]);
            }
        }
    }

    // s^(1/8) = sqrt(sqrt(sqrt(s))); relu fused (sums are >= 0).
#pragma unroll
    for (int p = 0; p < PIX; p++) {
        int ho = pix[p] / Wo, wo = pix[p] - ho * Wo;
        int oidx = ((b * O + o) * Ho + ho) * Wo + wo;
        float x0, x1;
        unpk(accc[p], x0, x1);
        ocp[oidx] = fmaxf(sqrtf(sqrtf(sqrtf(x0 + x1))), 0.f);
        unpk(accl[p], x0, x1);
        olp[oidx] = fmaxf(sqrtf(sqrtf(sqrtf(x0 + x1))), 0.f);
        unpk(acch[p], x0, x1);
        ohp[oidx] = fmaxf(sqrtf(sqrtf(sqrtf(x0 + x1))), 0.f);
    }
}

// 3x3 stride-2 VALID maxpool over all three bound tensors.
__global__ void maxpool_kernel(const float* __restrict__ ic,
                               const float* __restrict__ il,
                               const float* __restrict__ ih,
                               float* __restrict__ oc, float* __restrict__ ol,
                               float* __restrict__ oh, int BC, int H, int W,
                               int Ho, int Wo) {
    int i = blockIdx.x * blockDim.x + threadIdx.x;
    if (i >= BC * Ho * Wo) return;
    int wo = i % Wo;
    int t = i / Wo;
    int ho = t % Ho;
    int bc = t / Ho;
    int base = bc * H * W;
    float mc = -INFINITY, ml = -INFINITY, mh = -INFINITY;
#pragma unroll
    for (int ky = 0; ky < 3; ky++)
#pragma unroll
        for (int kx = 0; kx < 3; kx++) {
            int idx = base + (2 * ho + ky) * W + (2 * wo + kx);
            mc = fmaxf(mc, ic[idx]);
            ml = fmaxf(ml, il[idx]);
            mh = fmaxf(mh, ih[idx]);
        }
    oc[i] = mc;
    ol[i] = ml;
    oh[i] = mh;
}

// Interval-bound linear. Warp per (b, out_feature).
// mode 0: relu, write oc/ol/oh. mode 1: +bias, negate/swap into fout.
__global__ void linear_bound_kernel(
    const float* __restrict__ ic, const float* __restrict__ il,
    const float* __restrict__ ih, const float* __restrict__ Wm,
    const float* __restrict__ bias, float* __restrict__ oc,
    float* __restrict__ ol, float* __restrict__ oh, float* __restrict__ fout,
    int IN, int OUT, int B, int mode) {
    int gw = (blockIdx.x * blockDim.x + threadIdx.x) >> 5;
    int lane = threadIdx.x & 31;
    if (gw >= B * OUT) return;
    int b = gw / OUT;
    int j = gw - b * OUT;
    const float* wr = Wm + (size_t)j * IN;
    const float* pc = ic + (size_t)b * IN;
    const float* pl = il + (size_t)b * IN;
    const float* ph = ih + (size_t)b * IN;
    float sc = 0.f, sm = 0.f, sr = 0.f;
    for (int i = lane; i < IN; i += 32) {
        float w = wr[i];
        float cv = pc[i], lv = pl[i], hv = ph[i];
        sc = fmaf(cv, w, sc);
        sm = fmaf((lv + hv) * 0.5f, w, sm);
        sr = fmaf((hv - lv) * 0.5f, fabsf(w), sr);
    }
#pragma unroll
    for (int off = 16; off; off >>= 1) {
        sc += __shfl_xor_sync(0xffffffffu, sc, off);
        sm += __shfl_xor_sync(0xffffffffu, sm, off);
        sr += __shfl_xor_sync(0xffffffffu, sr, off);
    }
    if (lane == 0) {
        if (mode == 0) {
            oc[gw] = fmaxf(sc, 0.f);
            ol[gw] = fmaxf(sm - sr, 0.f);
            oh[gw] = fmaxf(sm + sr, 0.f);
        } else {
            float bj = bias[j];
            float c = sc + bj;
            float m = sm + bj;
            fout[gw] = -c;                       // -center
            fout[B * OUT + gw] = -(m + sr);      // -upper
            fout[2 * B * OUT + gw] = -(m - sr);  // -lower
        }
    }
}

static inline int cdiv(int a, int b) { return (a + b - 1) / b; }

extern "C" void kernel_launch(void* const* d_in, const int* in_sizes, int n_in,
                              void* d_out, int out_size) {
    const float* x = (const float*)d_in[0];
    const float* lo = (const float*)d_in[1];
    const float* hi = (const float*)d_in[2];
    const float* w1 = (const float*)d_in[3];
    const float* w2 = (const float*)d_in[4];
    const float* w3 = (const float*)d_in[5];
    const float* w4 = (const float*)d_in[6];
    const float* w5 = (const float*)d_in[7];
    const float* fw1 = (const float*)d_in[8];
    const float* fw2 = (const float*)d_in[9];
    const float* fw3 = (const float*)d_in[10];
    const float* fb3 = (const float*)d_in[11];
    float* out = (float*)d_out;

    float *ac, *al, *ah, *bc, *bl, *bh;
    float *w1t, *w2t, *w3t, *w4t, *w5t;
    cudaGetSymbolAddress((void**)&ac, g_ac);
    cudaGetSymbolAddress((void**)&al, g_al);
    cudaGetSymbolAddress((void**)&ah, g_ah);
    cudaGetSymbolAddress((void**)&bc, g_bc);
    cudaGetSymbolAddress((void**)&bl, g_bl);
    cudaGetSymbolAddress((void**)&bh, g_bh);
    cudaGetSymbolAddress((void**)&w1t, g_w1t);
    cudaGetSymbolAddress((void**)&w2t, g_w2t);
    cudaGetSymbolAddress((void**)&w3t, g_w3t);
    cudaGetSymbolAddress((void**)&w4t, g_w4t);
    cudaGetSymbolAddress((void**)&w5t, g_w5t);

    dim3 pb(32, 8);
    // pack: [O,F] -> negated pair-interleaved [FP/2][O][2]
    pack_weights<<<dim3(cdiv(148, 32), cdiv(96, 32)), pb>>>(w1, (float2*)w1t, 96, 147, 74);
    pack_weights<<<dim3(cdiv(2400, 32), cdiv(256, 32)), pb>>>(w2, (float2*)w2t, 256, 2400, 1200);
    pack_weights<<<dim3(cdiv(2304, 32), cdiv(384, 32)), pb>>>(w3, (float2*)w3t, 384, 2304, 1152);
    pack_weights<<<dim3(cdiv(3456, 32), cdiv(384, 32)), pb>>>(w4, (float2*)w4t, 384, 3456, 1728);
    pack_weights<<<dim3(cdiv(3456, 32), cdiv(256, 32)), pb>>>(w5, (float2*)w5t, 256, 3456, 1728);

    // conv1: [16,3,32,32] k7 s2 p2 -> [16,96,15,15] (F=147 padded to 148)
    ndconv_kernel<1, 3, 32, 32, 7, 2, 2, 96, 15, 15, 148, 148>
        <<<dim3(225, 16), 96>>>(x, lo, hi, w1t, ac, al, ah);
    // pool1: 15 -> 7
    maxpool_kernel<<<cdiv(16 * 96 * 49, 256), 256>>>(ac, al, ah, bc, bl, bh,
                                                     16 * 96, 15, 15, 7, 7);
    // conv2: k5 s1 p2 -> [16,256,7,7]; 2 pixels/block halves weight traffic
    ndconv_kernel<2, 96, 7, 7, 5, 1, 2, 256, 7, 7, 2400, 1200>
        <<<dim3(25, 16), 256>>>(bc, bl, bh, w2t, ac, al, ah);
    // pool2: 7 -> 3
    maxpool_kernel<<<cdiv(16 * 256 * 9, 256), 256>>>(ac, al, ah, bc, bl, bh,
                                                     16 * 256, 7, 7, 3, 3);
    // conv3: k3 s1 p1 -> [16,384,3,3]
    ndconv_kernel<1, 256, 3, 3, 3, 1, 1, 384, 3, 3, 2304, 2304>
        <<<dim3(9, 16), 384>>>(bc, bl, bh, w3t, ac, al, ah);
    // conv4
    ndconv_kernel<1, 384, 3, 3, 3, 1, 1, 384, 3, 3, 3456, 3456>
        <<<dim3(9, 16), 384>>>(ac, al, ah, w4t, bc, bl, bh);
    // conv5 -> [16,256,3,3] == [16,2304] flattened
    ndconv_kernel<1, 384, 3, 3, 3, 1, 1, 256, 3, 3, 3456, 3456>
        <<<dim3(9, 16), 256>>>(bc, bl, bh, w5t, ac, al, ah);

    // fc1: 2304 -> 1024 (+relu)
    linear_bound_kernel<<<cdiv(16 * 1024, 8), 256>>>(
        ac, al, ah, fw1, nullptr, bc, bl, bh, nullptr, 2304, 1024, 16, 0);
    // fc2: 1024 -> 512 (+relu)
    linear_bound_kernel<<<cdiv(16 * 512, 8), 256>>>(
        bc, bl, bh, fw2, nullptr, ac, al, ah, nullptr, 1024, 512, 16, 0);
    // fc3: 512 -> 10 (+bias), final negate/swap into d_out [(-c, -u, -l)]
    linear_bound_kernel<<<cdiv(16 * 10, 8), 256>>>(
        ac, al, ah, fw3, fb3, nullptr, nullptr, nullptr, out, 512, 10, 16, 1);
}

// round 11
// speedup vs baseline: 1.4837x; 1.1917x over previous
#include <cuda_runtime.h>
#include <math.h>

// ---------------------------------------------------------------------------
// NormDist-IBP AlexNet, f32x2 + quad-packed-weight edition.
//   5x Lp(p=8) distance convs with interval bounds (c,l,u), relu fused,
//   2x maxpool 3x3/s2, 3x interval-bound linear, final negate/swap.
// Weights pre-packed negated as [FP/4][O][4]: one LDG.128 per thread covers
// 4 F-taps; patches staged in smem and read as LDS.128 (float4).
// ---------------------------------------------------------------------------

using u64 = unsigned long long;

__device__ __forceinline__ u64 add2(u64 a, u64 b) {
    u64 d; asm("add.rn.f32x2 %0,%1,%2;" : "=l"(d) : "l"(a), "l"(b)); return d;
}
__device__ __forceinline__ u64 mul2(u64 a, u64 b) {
    u64 d; asm("mul.rn.f32x2 %0,%1,%2;" : "=l"(d) : "l"(a), "l"(b)); return d;
}
__device__ __forceinline__ u64 fma2(u64 a, u64 b, u64 c) {
    u64 d; asm("fma.rn.f32x2 %0,%1,%2,%3;" : "=l"(d) : "l"(a), "l"(b), "l"(c)); return d;
}
__device__ __forceinline__ void unpk(u64 v, float& lo, float& hi) {
    asm("mov.b64 {%0,%1},%2;" : "=f"(lo), "=f"(hi) : "l"(v));
}
__device__ __forceinline__ u64 pk2(float lo, float hi) {
    u64 d; asm("mov.b64 %0,{%1,%2};" : "=l"(d) : "f"(lo), "f"(hi)); return d;
}

#define MAXBUF 345600  // 16*96*15*15 (largest intermediate)

__device__ float g_ac[MAXBUF], g_al[MAXBUF], g_ah[MAXBUF];
__device__ float g_bc[MAXBUF], g_bl[MAXBUF], g_bh[MAXBUF];
__device__ float4 g_w1t[37 * 96];
__device__ float4 g_w2t[600 * 256];
__device__ float4 g_w3t[576 * 384];
__device__ float4 g_w4t[864 * 384];
__device__ float4 g_w5t[864 * 256];

// [O, F] -> negated quad-interleaved [JQ][O][4], tiled through smem so both
// sides are coalesced. Pads f in [F, 4*JQ) with 0.
__global__ void pack_weights(const float* __restrict__ w, float4* __restrict__ dst,
                             int O, int F, int JQ /* = FP/4 */) {
    __shared__ float tile[32][33];
    int fb = blockIdx.x * 32, ob = blockIdx.y * 32;
    int tx = threadIdx.x, ty = threadIdx.y;  // 32 x 8
#pragma unroll
    for (int r = 0; r < 32; r += 8) {
        int o = ob + ty + r, f = fb + tx;
        tile[ty + r][tx] = (o < O && f < F) ? -w[(size_t)o * F + f] : 0.f;
    }
    __syncthreads();
    int tid = ty * 32 + tx;
#pragma unroll
    for (int pass = 0; pass < 4; pass++) {
        int idx = pass * 256 + tid;   // 0..1023 covers 8 quads x 32 o x 4
        int jl = idx >> 7;
        int rem = idx & 127;
        int ol = rem >> 2, m = rem & 3;
        int j = (fb >> 2) + jl;
        int o = ob + ol;
        if (o < O && j < JQ)
            ((float*)dst)[((size_t)j * O + o) * 4 + m] = tile[ol][jl * 4 + m];
    }
}

// One f32x2 pair of taps for all three bound paths.
__device__ __forceinline__ void pairstep(u64 w, float pc0, float pc1, float pl0,
                                         float pl1, float ph0, float ph1,
                                         u64& ac, u64& al, u64& ah) {
    u64 s1 = add2(pk2(pc0, pc1), w);  // pc - w   (w stored negated)
    u64 s2 = add2(pk2(pl0, pl1), w);  // pl - w
    u64 s3 = add2(pk2(ph0, ph1), w);  // ph - w
    // center: (pc-w)^8
    u64 c2 = mul2(s1, s1);
    u64 c4 = mul2(c2, c2);
    ac = fma2(c4, c4, ac);
    // upper: max(|s2|,|s3|)^8 via max of squares
    u64 a = mul2(s2, s2);
    u64 b = mul2(s3, s3);
    float a0, a1, b0, b1;
    unpk(a, a0, a1);
    unpk(b, b0, b1);
    u64 h2 = pk2(fmaxf(a0, b0), fmaxf(a1, b1));
    u64 h4 = mul2(h2, h2);
    ah = fma2(h4, h4, ah);
    // lower: max(s2, -s3, 0)^8
    float s20, s21, s30, s31;
    unpk(s2, s20, s21);
    unpk(s3, s30, s31);
    u64 dl = pk2(fmaxf(fmaxf(s20, -s30), 0.f), fmaxf(fmaxf(s21, -s31), 0.f));
    u64 l2 = mul2(dl, dl);
    u64 l4 = mul2(l2, l2);
    al = fma2(l4, l4, al);
}

// NormDist conv + fused relu. Block: (batch, PIX output pixels).
// Thread: one output channel.
template <int PIX, int C, int H, int W, int K, int S, int PAD, int O, int Ho,
          int Wo, int FP, int FT>
__global__ void __launch_bounds__(O) ndconv_kernel(
    const float* __restrict__ ic, const float* __restrict__ il,
    const float* __restrict__ ih, const float4* __restrict__ wt,
    float* __restrict__ ocp, float* __restrict__ olp, float* __restrict__ ohp) {
    static_assert(FP % FT == 0 && FT % 4 == 0, "tile must divide padded F");
    constexpr int F = C * K * K;
    constexpr int L = Ho * Wo;
    __shared__ alignas(16) float spc[PIX][FT], spl[PIX][FT], sph[PIX][FT];

    const int b = blockIdx.y;
    const int o = threadIdx.x;
    int pix[PIX];
    pix[0] = blockIdx.x * PIX;
#pragma unroll
    for (int p = 1; p < PIX; p++) pix[p] = min(pix[0] + p, L - 1);

    u64 accc[PIX], accl[PIX], acch[PIX];
#pragma unroll
    for (int p = 0; p < PIX; p++) accc[p] = accl[p] = acch[p] = 0ull;

    for (int fbase = 0; fbase < FP; fbase += FT) {
        __syncthreads();
#pragma unroll
        for (int p = 0; p < PIX; p++) {
            int ho = pix[p] / Wo, wo = pix[p] - ho * Wo;
            for (int t = threadIdx.x; t < FT; t += O) {
                int f = fbase + t;
                float vc = 0.f, vl = 0.f, vh = 0.f;
                if (f < F) {
                    int cch = f / (K * K);
                    int r = f - cch * (K * K);
                    int ky = r / K, kx = r - ky * K;
                    int y = ho * S - PAD + ky;
                    int x = wo * S - PAD + kx;
                    if ((unsigned)y < (unsigned)H && (unsigned)x < (unsigned)W) {
                        int idx = ((b * C + cch) * H + y) * W + x;
                        vc = ic[idx]; vl = il[idx]; vh = ih[idx];
                    }
                }
                spc[p][t] = vc; spl[p][t] = vl; sph[p][t] = vh;
            }
        }
        __syncthreads();

        const float4* wq = wt + (size_t)(fbase >> 2) * O + o;
#define ND_BODY(tj)                                                          \
    {                                                                        \
        float4 wv = __ldg(wq + (size_t)(tj) * O);                            \
        u64 w01 = pk2(wv.x, wv.y), w23 = pk2(wv.z, wv.w);                    \
        _Pragma("unroll") for (int p = 0; p < PIX; p++) {                    \
            float4 cc = ((const float4*)spc[p])[tj];                         \
            float4 ll = ((const float4*)spl[p])[tj];                         \
            float4 hh = ((const float4*)sph[p])[tj];                         \
            pairstep(w01, cc.x, cc.y, ll.x, ll.y, hh.x, hh.y, accc[p],       \
                     accl[p], acch[p]);                                      \
            pairstep(w23, cc.z, cc.w, ll.z, ll.w, hh.z, hh.w, accc[p],       \
                     accl[p], acch[p]);                                      \
        }                                                                    \
    }
        if constexpr (PIX == 1) {
#pragma unroll 4
            for (int tj = 0; tj < FT / 4; tj++) ND_BODY(tj);
        } else {
#pragma unroll 2
            for (int tj = 0; tj < FT / 4; tj++) ND_BODY(tj);
        }
#undef ND_BODY
    }

    // s^(1/8) = sqrt(sqrt(sqrt(s))); relu fused (sums >= 0).
#pragma unroll
    for (int p = 0; p < PIX; p++) {
        int ho = pix[p] / Wo, wo = pix[p] - ho * Wo;
        int oidx = ((b * O + o) * Ho + ho) * Wo + wo;
        float x0, x1;
        unpk(accc[p], x0, x1);
        ocp[oidx] = fmaxf(sqrtf(sqrtf(sqrtf(x0 + x1))), 0.f);
        unpk(accl[p], x0, x1);
        olp[oidx] = fmaxf(sqrtf(sqrtf(sqrtf(x0 + x1))), 0.f);
        unpk(acch[p], x0, x1);
        ohp[oidx] = fmaxf(sqrtf(sqrtf(sqrtf(x0 + x1))), 0.f);
    }
}

// 3x3 stride-2 VALID maxpool over all three bound tensors.
__global__ void maxpool_kernel(const float* __restrict__ ic,
                               const float* __restrict__ il,
                               const float* __restrict__ ih,
                               float* __restrict__ oc, float* __restrict__ ol,
                               float* __restrict__ oh, int BC, int H, int W,
                               int Ho, int Wo) {
    int i = blockIdx.x * blockDim.x + threadIdx.x;
    if (i >= BC * Ho * Wo) return;
    int wo = i % Wo;
    int t = i / Wo;
    int ho = t % Ho;
    int bc = t / Ho;
    int base = bc * H * W;
    float mc = -INFINITY, ml = -INFINITY, mh = -INFINITY;
#pragma unroll
    for (int ky = 0; ky < 3; ky++)
#pragma unroll
        for (int kx = 0; kx < 3; kx++) {
            int idx = base + (2 * ho + ky) * W + (2 * wo + kx);
            mc = fmaxf(mc, ic[idx]);
            ml = fmaxf(ml, il[idx]);
            mh = fmaxf(mh, ih[idx]);
        }
    oc[i] = mc;
    ol[i] = ml;
    oh[i] = mh;
}

// Interval-bound linear. Warp per (b, out_feature).
// mode 0: relu, write oc/ol/oh. mode 1: +bias, negate/swap into fout.
__global__ void linear_bound_kernel(
    const float* __restrict__ ic, const float* __restrict__ il,
    const float* __restrict__ ih, const float* __restrict__ Wm,
    const float* __restrict__ bias, float* __restrict__ oc,
    float* __restrict__ ol, float* __restrict__ oh, float* __restrict__ fout,
    int IN, int OUT, int B, int mode) {
    int gw = (blockIdx.x * blockDim.x + threadIdx.x) >> 5;
    int lane = threadIdx.x & 31;
    if (gw >= B * OUT) return;
    int b = gw / OUT;
    int j = gw - b * OUT;
    const float* wr = Wm + (size_t)j * IN;
    const float* pc = ic + (size_t)b * IN;
    const float* pl = il + (size_t)b * IN;
    const float* ph = ih + (size_t)b * IN;
    float sc = 0.f, sm = 0.f, sr = 0.f;
    for (int i = lane; i < IN; i += 32) {
        float w = wr[i];
        float cv = pc[i], lv = pl[i], hv = ph[i];
        sc = fmaf(cv, w, sc);
        sm = fmaf((lv + hv) * 0.5f, w, sm);
        sr = fmaf((hv - lv) * 0.5f, fabsf(w), sr);
    }
#pragma unroll
    for (int off = 16; off; off >>= 1) {
        sc += __shfl_xor_sync(0xffffffffu, sc, off);
        sm += __shfl_xor_sync(0xffffffffu, sm, off);
        sr += __shfl_xor_sync(0xffffffffu, sr, off);
    }
    if (lane == 0) {
        if (mode == 0) {
            oc[gw] = fmaxf(sc, 0.f);
            ol[gw] = fmaxf(sm - sr, 0.f);
            oh[gw] = fmaxf(sm + sr, 0.f);
        } else {
            float bj = bias[j];
            float c = sc + bj;
            float m = sm + bj;
            fout[gw] = -c;                       // -center
            fout[B * OUT + gw] = -(m + sr);      // -upper
            fout[2 * B * OUT + gw] = -(m - sr);  // -lower
        }
    }
}

static inline int cdiv(int a, int b) { return (a + b - 1) / b; }

extern "C" void kernel_launch(void* const* d_in, const int* in_sizes, int n_in,
                              void* d_out, int out_size) {
    const float* x = (const float*)d_in[0];
    const float* lo = (const float*)d_in[1];
    const float* hi = (const float*)d_in[2];
    const float* w1 = (const float*)d_in[3];
    const float* w2 = (const float*)d_in[4];
    const float* w3 = (const float*)d_in[5];
    const float* w4 = (const float*)d_in[6];
    const float* w5 = (const float*)d_in[7];
    const float* fw1 = (const float*)d_in[8];
    const float* fw2 = (const float*)d_in[9];
    const float* fw3 = (const float*)d_in[10];
    const float* fb3 = (const float*)d_in[11];
    float* out = (float*)d_out;

    float *ac, *al, *ah, *bc, *bl, *bh;
    float4 *w1t, *w2t, *w3t, *w4t, *w5t;
    cudaGetSymbolAddress((void**)&ac, g_ac);
    cudaGetSymbolAddress((void**)&al, g_al);
    cudaGetSymbolAddress((void**)&ah, g_ah);
    cudaGetSymbolAddress((void**)&bc, g_bc);
    cudaGetSymbolAddress((void**)&bl, g_bl);
    cudaGetSymbolAddress((void**)&bh, g_bh);
    cudaGetSymbolAddress((void**)&w1t, g_w1t);
    cudaGetSymbolAddress((void**)&w2t, g_w2t);
    cudaGetSymbolAddress((void**)&w3t, g_w3t);
    cudaGetSymbolAddress((void**)&w4t, g_w4t);
    cudaGetSymbolAddress((void**)&w5t, g_w5t);

    dim3 pb(32, 8);
    pack_weights<<<dim3(cdiv(148, 32), cdiv(96, 32)), pb>>>(w1, w1t, 96, 147, 37);
    pack_weights<<<dim3(cdiv(2400, 32), cdiv(256, 32)), pb>>>(w2, w2t, 256, 2400, 600);
    pack_weights<<<dim3(cdiv(2304, 32), cdiv(384, 32)), pb>>>(w3, w3t, 384, 2304, 576);
    pack_weights<<<dim3(cdiv(3456, 32), cdiv(384, 32)), pb>>>(w4, w4t, 384, 3456, 864);
    pack_weights<<<dim3(cdiv(3456, 32), cdiv(256, 32)), pb>>>(w5, w5t, 256, 3456, 864);

    // conv1: [16,3,32,32] k7 s2 p2 -> [16,96,15,15], PIX=5 (L=225)
    ndconv_kernel<5, 3, 32, 32, 7, 2, 2, 96, 15, 15, 148, 148>
        <<<dim3(45, 16), 96>>>(x, lo, hi, w1t, ac, al, ah);
    // pool1: 15 -> 7
    maxpool_kernel<<<cdiv(16 * 96 * 49, 256), 256>>>(ac, al, ah, bc, bl, bh,
                                                     16 * 96, 15, 15, 7, 7);
    // conv2: k5 s1 p2 -> [16,256,7,7], PIX=4 (L=49 -> 13 pixblocks)
    ndconv_kernel<4, 96, 7, 7, 5, 1, 2, 256, 7, 7, 2400, 800>
        <<<dim3(13, 16), 256>>>(bc, bl, bh, w2t, ac, al, ah);
    // pool2: 7 -> 3
    maxpool_kernel<<<cdiv(16 * 256 * 9, 256), 256>>>(ac, al, ah, bc, bl, bh,
                                                     16 * 256, 7, 7, 3, 3);
    // conv3: k3 s1 p1 -> [16,384,3,3]
    ndconv_kernel<1, 256, 3, 3, 3, 1, 1, 384, 3, 3, 2304, 2304>
        <<<dim3(9, 16), 384>>>(bc, bl, bh, w3t, ac, al, ah);
    // conv4
    ndconv_kernel<1, 384, 3, 3, 3, 1, 1, 384, 3, 3, 3456, 3456>
        <<<dim3(9, 16), 384>>>(ac, al, ah, w4t, bc, bl, bh);
    // conv5 -> [16,256,3,3] == [16,2304] flattened
    ndconv_kernel<1, 384, 3, 3, 3, 1, 1, 256, 3, 3, 3456, 3456>
        <<<dim3(9, 16), 256>>>(bc, bl, bh, w5t, ac, al, ah);

    // fc1: 2304 -> 1024 (+relu)
    linear_bound_kernel<<<cdiv(16 * 1024, 8), 256>>>(
        ac, al, ah, fw1, nullptr, bc, bl, bh, nullptr, 2304, 1024, 16, 0);
    // fc2: 1024 -> 512 (+relu)
    linear_bound_kernel<<<cdiv(16 * 512, 8), 256>>>(
        bc, bl, bh, fw2, nullptr, ac, al, ah, nullptr, 1024, 512, 16, 0);
    // fc3: 512 -> 10 (+bias), final negate/swap into d_out [(-c, -u, -l)]
    linear_bound_kernel<<<cdiv(16 * 10, 8), 256>>>(
        ac, al, ah, fw3, fb3, nullptr, nullptr, nullptr, out, 512, 10, 16, 1);
}